// round 10
// baseline (speedup 1.0000x reference)
#include <cuda_runtime.h>
#include <cuda_fp16.h>
#include <math.h>
#include <stdint.h>

#define NNODE 16384
#define NEDGE 1048576
#define NLOOP (NEDGE + NNODE)
#define NIN 256
#define NHID 64
#define ZH_LD 72    // halfs per smem row (144 B stride -> ldmatrix conflict-free)
#define LDST 129    // staging stride (mod 32 == 1 -> transposed reads conflict-free)

// ---------------- scratch (static device memory; no runtime alloc) ----------
__device__ int    g_cnt[NNODE];
__device__ int    g_rowptr[NNODE + 1];
__device__ int    g_off[NNODE];
__device__ int    g_col[NLOOP];
__device__ float  g_dinv[NNODE];
__device__ float  g_t[NNODE * NIN];      // fp32 scratch (decoder pre-GEMM feats)
__device__ __half g_th[NNODE * NHID];    // fp16 pre-aggregation features
__device__ float  g_h[NNODE * NHID];
__device__ float  g_z[NNODE * NHID];
__device__ __half g_zh[NNODE * NHID];

// ---------------- ptx helpers ----------------
__device__ __forceinline__ void ldsm_x4(uint32_t r[4], uint32_t addr) {
    asm volatile("ldmatrix.sync.aligned.m8n8.x4.shared.b16 {%0,%1,%2,%3}, [%4];"
                 : "=r"(r[0]), "=r"(r[1]), "=r"(r[2]), "=r"(r[3]) : "r"(addr));
}
__device__ __forceinline__ void mma_f16(float c[4], const uint32_t a[4],
                                        uint32_t b0, uint32_t b1) {
    asm volatile(
        "mma.sync.aligned.m16n8k16.row.col.f32.f16.f16.f32 "
        "{%0,%1,%2,%3},{%4,%5,%6,%7},{%8,%9},{%0,%1,%2,%3};"
        : "+f"(c[0]), "+f"(c[1]), "+f"(c[2]), "+f"(c[3])
        : "r"(a[0]), "r"(a[1]), "r"(a[2]), "r"(a[3]), "r"(b0), "r"(b1));
}

// ---------------- CSR build ----------------
__global__ void k_init_cnt() {
    int i = blockIdx.x * blockDim.x + threadIdx.x;
    if (i < NNODE) g_cnt[i] = 1;  // self-loop
}

__global__ void k_hist(const int* __restrict__ ei) {
    int e = blockIdx.x * blockDim.x + threadIdx.x;
    if (e < NEDGE) atomicAdd(&g_cnt[ei[NEDGE + e]], 1);  // dst row
}

__global__ void k_scan() {
    __shared__ int s[1024];
    int tid = threadIdx.x;
    int base = tid * 16;
    int v[16];
    int tot = 0;
#pragma unroll
    for (int j = 0; j < 16; j++) { v[j] = g_cnt[base + j]; tot += v[j]; }
    s[tid] = tot;
    __syncthreads();
    for (int o = 1; o < 1024; o <<= 1) {
        int add = (tid >= o) ? s[tid - o] : 0;
        __syncthreads();
        s[tid] += add;
        __syncthreads();
    }
    int run = (tid == 0) ? 0 : s[tid - 1];
#pragma unroll
    for (int j = 0; j < 16; j++) {
        g_rowptr[base + j] = run;
        g_off[base + j] = run;
        g_dinv[base + j] = rsqrtf((float)v[j]);
        run += v[j];
    }
    if (tid == 1023) g_rowptr[NNODE] = s[1023];
}

__global__ void k_scatter(const int* __restrict__ ei) {
    int idx = blockIdx.x * blockDim.x + threadIdx.x;
    if (idx >= NLOOP) return;
    int s, d;
    if (idx < NEDGE) { s = ei[idx]; d = ei[NEDGE + idx]; }
    else             { s = idx - NEDGE; d = s; }
    int p = atomicAdd(&g_off[d], 1);
    g_col[p] = s;
}

// ---------------- dense GEMM: C[M,NC] = A[M,K] @ W[K,NC] --------------------
// EPI: +bias & relu (fp32 out). HOUT: write fp16 (no bias).
template <int K, int NC, bool EPI, bool HOUT>
__global__ void k_gemm_nn(const float* __restrict__ A, const float* __restrict__ W,
                          void* __restrict__ Cv, const float* __restrict__ bias) {
    __shared__ float As[32][68];
    __shared__ float Bs[32][64];
    const int tx = threadIdx.x & 15, ty = threadIdx.x >> 4;
    const int bm = blockIdx.y * 64, bn = blockIdx.x * 64;
    float acc[4][4] = {};
    for (int k0 = 0; k0 < K; k0 += 32) {
#pragma unroll
        for (int i = 0; i < 2; i++) {
            int idx = threadIdx.x + i * 256;
            int r = idx >> 3, kc = (idx & 7) * 4;
            float4 v = *(const float4*)&A[(bm + r) * K + k0 + kc];
            As[kc + 0][r] = v.x; As[kc + 1][r] = v.y;
            As[kc + 2][r] = v.z; As[kc + 3][r] = v.w;
        }
#pragma unroll
        for (int i = 0; i < 2; i++) {
            int idx = threadIdx.x + i * 256;
            int r = idx >> 4, c = (idx & 15) * 4;
            *(float4*)&Bs[r][c] = *(const float4*)&W[(k0 + r) * NC + bn + c];
        }
        __syncthreads();
#pragma unroll
        for (int kk = 0; kk < 32; kk++) {
            float a[4], b[4];
            *(float4*)a = *(const float4*)&As[kk][ty * 4];
            *(float4*)b = *(const float4*)&Bs[kk][tx * 4];
#pragma unroll
            for (int i = 0; i < 4; i++)
#pragma unroll
                for (int j = 0; j < 4; j++) acc[i][j] += a[i] * b[j];
        }
        __syncthreads();
    }
#pragma unroll
    for (int i = 0; i < 4; i++) {
        int row = bm + ty * 4 + i, col = bn + tx * 4;
        if (HOUT) {
            __half* Ch = (__half*)Cv;
            __half2 p0 = __floats2half2_rn(acc[i][0], acc[i][1]);
            __half2 p1 = __floats2half2_rn(acc[i][2], acc[i][3]);
            *(__half2*)&Ch[row * NC + col] = p0;
            *(__half2*)&Ch[row * NC + col + 2] = p1;
        } else {
            float* C = (float*)Cv;
            float4 o;
            float* po = (float*)&o;
#pragma unroll
            for (int j = 0; j < 4; j++) {
                float v = acc[i][j];
                if (EPI) v = fmaxf(v + bias[col + j], 0.f);
                po[j] = v;
            }
            *(float4*)&C[row * NC + col] = o;
        }
    }
}

// ---------------- CSR aggregation from fp16 rows (F=64) ---------------------
// one warp per node; lane covers cols {2*lane, 2*lane+1}; fp32 accumulate.
template <bool BR>
__global__ void k_agg_h64(const __half* __restrict__ t,
                          const float* __restrict__ bias,
                          float* __restrict__ out) {
    int warp = (blockIdx.x * blockDim.x + threadIdx.x) >> 5;
    int lane = threadIdx.x & 31;
    if (warp >= NNODE) return;
    int e = g_rowptr[warp], end = g_rowptr[warp + 1];
    int c0 = lane * 2;
    float ax = 0.f, ay = 0.f;
    for (; e < end; e++) {
        int s = __ldg(&g_col[e]);
        float w = __ldg(&g_dinv[s]);
        __half2 hv = __ldg((const __half2*)&t[s * NHID + c0]);
        float2 f = __half22float2(hv);
        ax += w * f.x;
        ay += w * f.y;
    }
    float di = __ldg(&g_dinv[warp]);
    float2 v = make_float2(ax * di, ay * di);
    if (BR) {
        v.x = fmaxf(v.x + __ldg(&bias[c0]), 0.f);
        v.y = fmaxf(v.y + __ldg(&bias[c0 + 1]), 0.f);
    }
    *(float2*)&out[warp * NHID + c0] = v;
}

// ---------------- z (fp32) -> zh (fp16) pre-pass ----------------------------
__global__ void k_z2h(const float* __restrict__ z, __half* __restrict__ zh) {
    int i = blockIdx.x * blockDim.x + threadIdx.x;  // over float2 pairs
    float2 v = *(const float2*)&z[(size_t)i * 2];
    *(__half2*)&zh[(size_t)i * 2] = __floats2half2_rn(v.x, v.y);
}

// ---------------- z @ z.T via fp16 mma (symmetric, lower-tri compute) -------
// 128x128 tile per block, 8 warps (4x2), warp tile 32x64, K=64 in 4 k16 steps.
__global__ void k_zzt_hmma(const __half* __restrict__ Zh, float* __restrict__ C) {
    const int ti = blockIdx.y, tj = blockIdx.x;
    if (tj > ti) return;
    extern __shared__ float sm[];
    __half* Za = (__half*)sm;                 // [128][ZH_LD]
    __half* Zb = (__half*)sm + 128 * ZH_LD;   // [128][ZH_LD]
    const int tid = threadIdx.x;
    const int lane = tid & 31, warp = tid >> 5;
    const int wm = warp >> 1, wn = warp & 1;
    const int m0 = wm * 32, n0 = wn * 64;

#pragma unroll
    for (int i = 0; i < 4; i++) {
        int idx = tid + i * 256;
        int r = idx >> 3, c8 = (idx & 7) * 8;   // 8 halfs = 16 B
        uint4 va = *(const uint4*)&Zh[(size_t)(ti * 128 + r) * 64 + c8];
        uint4 vb = *(const uint4*)&Zh[(size_t)(tj * 128 + r) * 64 + c8];
        *(uint4*)&Za[r * ZH_LD + c8] = va;
        *(uint4*)&Zb[r * ZH_LD + c8] = vb;
    }
    __syncthreads();

    uint32_t a_base = (uint32_t)__cvta_generic_to_shared(Za);
    uint32_t b_base = (uint32_t)__cvta_generic_to_shared(Zb);
    float acc[2][8][4] = {};
#pragma unroll
    for (int ks = 0; ks < 4; ks++) {
        const int k0 = ks * 16;
        uint32_t a[2][4];
#pragma unroll
        for (int f = 0; f < 2; f++) {
            int r = m0 + f * 16 + (lane & 7) + ((lane & 8) ? 8 : 0);
            int kk = k0 + ((lane & 16) ? 8 : 0);
            ldsm_x4(a[f], a_base + (uint32_t)(r * ZH_LD + kk) * 2u);
        }
        uint32_t b[4][4];
#pragma unroll
        for (int p = 0; p < 4; p++) {
            int r = n0 + p * 16 + (lane & 7) + ((lane & 16) ? 8 : 0);
            int kk = k0 + ((lane & 8) ? 8 : 0);
            ldsm_x4(b[p], b_base + (uint32_t)(r * ZH_LD + kk) * 2u);
        }
#pragma unroll
        for (int f = 0; f < 2; f++)
#pragma unroll
            for (int j = 0; j < 8; j++)
                mma_f16(acc[f][j], a[f], b[j >> 1][(j & 1) * 2], b[j >> 1][(j & 1) * 2 + 1]);
    }

    // direct write of tile (ti, tj)
    const int mrow = lane >> 2, ncol2 = (lane & 3) * 2;
#pragma unroll
    for (int f = 0; f < 2; f++) {
        int row0 = ti * 128 + m0 + f * 16 + mrow;
#pragma unroll
        for (int j = 0; j < 8; j++) {
            int col = tj * 128 + n0 + j * 8 + ncol2;
            *(float2*)&C[(size_t)row0 * NNODE + col] =
                make_float2(acc[f][j][0], acc[f][j][1]);
            *(float2*)&C[(size_t)(row0 + 8) * NNODE + col] =
                make_float2(acc[f][j][2], acc[f][j][3]);
        }
    }
    if (ti == tj) return;

    // mirror tile (tj, ti): stride-129 staging -> conflict-free transposed reads
    __syncthreads();
    float* S = sm;  // 128 * 129 floats = 66048 B
#pragma unroll
    for (int f = 0; f < 2; f++) {
        int r = m0 + f * 16 + mrow;
#pragma unroll
        for (int j = 0; j < 8; j++) {
            int c = n0 + j * 8 + ncol2;
            S[r * LDST + c] = acc[f][j][0];
            S[r * LDST + c + 1] = acc[f][j][1];
            S[(r + 8) * LDST + c] = acc[f][j][2];
            S[(r + 8) * LDST + c + 1] = acc[f][j][3];
        }
    }
    __syncthreads();
#pragma unroll
    for (int i = 0; i < 16; i++) {
        int y = warp * 16 + i;
        size_t rowbase = (size_t)(tj * 128 + y) * NNODE + ti * 128;
#pragma unroll
        for (int k = 0; k < 4; k++) {
            int col = lane + 32 * k;
            __stcs(&C[rowbase + col], S[col * LDST + y]);
        }
    }
}

// ---------------- launch ----------------------------------------------------
extern "C" void kernel_launch(void* const* d_in, const int* in_sizes, int n_in,
                              void* d_out, int out_size) {
    const float* x  = (const float*)d_in[0];
    const int*   ei = (const int*)d_in[1];
    const float* W1 = (const float*)d_in[2];
    const float* b1 = (const float*)d_in[3];
    const float* W2 = (const float*)d_in[4];
    const float* b2 = (const float*)d_in[5];
    const float* Wd = (const float*)d_in[6];
    const float* bd = (const float*)d_in[7];
    float* out = (float*)d_out;
    float* xhat = out + (size_t)NNODE * NNODE;

    float*  t;  cudaGetSymbolAddress((void**)&t,  g_t);
    __half* th; cudaGetSymbolAddress((void**)&th, g_th);
    float*  h;  cudaGetSymbolAddress((void**)&h,  g_h);
    float*  z;  cudaGetSymbolAddress((void**)&z,  g_z);
    __half* zh; cudaGetSymbolAddress((void**)&zh, g_zh);

    const int zzt_smem = 128 * LDST * (int)sizeof(float);  // 66048
    cudaFuncSetAttribute(k_zzt_hmma, cudaFuncAttributeMaxDynamicSharedMemorySize,
                         zzt_smem);

    // one-time side resources (no device memory)
    struct Res {
        cudaStream_t sB;
        cudaEvent_t evA, evB;
        Res() {
            cudaStreamCreateWithFlags(&sB, cudaStreamNonBlocking);
            cudaEventCreateWithFlags(&evA, cudaEventDisableTiming);
            cudaEventCreateWithFlags(&evB, cudaEventDisableTiming);
        }
    };
    static Res R;

    // ---- fork: CSR build on sB, concurrent with x@W1 on main stream ----
    cudaEventRecord(R.evA, 0);
    cudaStreamWaitEvent(R.sB, R.evA, 0);
    k_init_cnt<<<NNODE / 256, 256, 0, R.sB>>>();
    k_hist<<<NEDGE / 256, 256, 0, R.sB>>>(ei);
    k_scan<<<1, 1024, 0, R.sB>>>();
    k_scatter<<<(NLOOP + 255) / 256, 256, 0, R.sB>>>(ei);
    cudaEventRecord(R.evB, R.sB);

    // layer-1 feature transform, fp16 output
    k_gemm_nn<NIN, NHID, false, true><<<dim3(1, NNODE / 64), 256>>>(x, W1, th, nullptr);

    // ---- join: encoder chain needs CSR + th ----
    cudaStreamWaitEvent(0, R.evB, 0);
    k_agg_h64<true><<<NNODE * 32 / 256, 256>>>(th, b1, h);
    k_gemm_nn<NHID, NHID, false, true><<<dim3(1, NNODE / 64), 256>>>(h, W2, th, nullptr);
    k_agg_h64<true><<<NNODE * 32 / 256, 256>>>(th, b2, z);

    // z -> fp16 (used by decoder agg AND structure decoder)
    k_z2h<<<NNODE * NHID / 2 / 256, 256>>>(z, zh);

    // attribute decoder (serial — overlapping with zzt thrashes L2)
    k_agg_h64<false><<<NNODE * 32 / 256, 256>>>(zh, nullptr, t);
    k_gemm_nn<NHID, NIN, true, false><<<dim3(NIN / 64, NNODE / 64), 256>>>(t, Wd, xhat, bd);

    // structure decoder: out = z @ z.T (symmetric, fp16 tensor path, f32 accum)
    k_zzt_hmma<<<dim3(NNODE / 128, NNODE / 128), 256, zzt_smem>>>(zh, out);
}

// round 12
// speedup vs baseline: 1.0250x; 1.0250x over previous
#include <cuda_runtime.h>
#include <cuda_fp16.h>
#include <math.h>
#include <stdint.h>

#define NNODE 16384
#define NEDGE 1048576
#define NLOOP (NEDGE + NNODE)
#define NIN 256
#define NHID 64
#define ZH_LD 72    // halfs per smem row (144 B stride -> ldmatrix conflict-free)
#define LDST 129    // staging stride (mod 32 == 1 -> transposed reads conflict-free)

// ---------------- scratch (static device memory; no runtime alloc) ----------
__device__ int    g_cnt[NNODE];
__device__ int    g_rowptr[NNODE + 1];
__device__ int    g_off[NNODE];
__device__ int    g_col[NLOOP];
__device__ float  g_dinv[NNODE];
__device__ float  g_t[NNODE * NIN];      // fp32 scratch (decoder pre-GEMM feats)
__device__ __half g_th[NNODE * NHID];    // fp16 pre-aggregation features
__device__ float  g_h[NNODE * NHID];
__device__ __half g_zh[NNODE * NHID];    // fp16 latent z

// ---------------- ptx helpers ----------------
__device__ __forceinline__ void ldsm_x4(uint32_t r[4], uint32_t addr) {
    asm volatile("ldmatrix.sync.aligned.m8n8.x4.shared.b16 {%0,%1,%2,%3}, [%4];"
                 : "=r"(r[0]), "=r"(r[1]), "=r"(r[2]), "=r"(r[3]) : "r"(addr));
}
__device__ __forceinline__ void mma_f16(float c[4], const uint32_t a[4],
                                        uint32_t b0, uint32_t b1) {
    asm volatile(
        "mma.sync.aligned.m16n8k16.row.col.f32.f16.f16.f32 "
        "{%0,%1,%2,%3},{%4,%5,%6,%7},{%8,%9},{%0,%1,%2,%3};"
        : "+f"(c[0]), "+f"(c[1]), "+f"(c[2]), "+f"(c[3])
        : "r"(a[0]), "r"(a[1]), "r"(a[2]), "r"(a[3]), "r"(b0), "r"(b1));
}

// ---------------- CSR build ----------------
__global__ void k_init_cnt() {
    int i = blockIdx.x * blockDim.x + threadIdx.x;
    if (i < NNODE) g_cnt[i] = 1;  // self-loop
}

__global__ void k_hist(const int* __restrict__ ei) {
    int e = blockIdx.x * blockDim.x + threadIdx.x;
    if (e < NEDGE) atomicAdd(&g_cnt[ei[NEDGE + e]], 1);  // dst row
}

__global__ void k_scan() {
    __shared__ int s[1024];
    int tid = threadIdx.x;
    int base = tid * 16;
    int v[16];
    int tot = 0;
#pragma unroll
    for (int j = 0; j < 16; j++) { v[j] = g_cnt[base + j]; tot += v[j]; }
    s[tid] = tot;
    __syncthreads();
    for (int o = 1; o < 1024; o <<= 1) {
        int add = (tid >= o) ? s[tid - o] : 0;
        __syncthreads();
        s[tid] += add;
        __syncthreads();
    }
    int run = (tid == 0) ? 0 : s[tid - 1];
#pragma unroll
    for (int j = 0; j < 16; j++) {
        g_rowptr[base + j] = run;
        g_off[base + j] = run;
        g_dinv[base + j] = rsqrtf((float)v[j]);
        run += v[j];
    }
    if (tid == 1023) g_rowptr[NNODE] = s[1023];
}

__global__ void k_scatter(const int* __restrict__ ei) {
    int idx = blockIdx.x * blockDim.x + threadIdx.x;
    if (idx >= NLOOP) return;
    int s, d;
    if (idx < NEDGE) { s = ei[idx]; d = ei[NEDGE + idx]; }
    else             { s = idx - NEDGE; d = s; }
    int p = atomicAdd(&g_off[d], 1);
    g_col[p] = s;
}

// ---------------- dense GEMM: C[M,NC] = A[M,K] @ W[K,NC] --------------------
// EPI: +bias & relu (fp32 out). HOUT: write fp16 (no bias).
template <int K, int NC, bool EPI, bool HOUT>
__global__ void k_gemm_nn(const float* __restrict__ A, const float* __restrict__ W,
                          void* __restrict__ Cv, const float* __restrict__ bias) {
    __shared__ float As[32][68];
    __shared__ float Bs[32][64];
    const int tx = threadIdx.x & 15, ty = threadIdx.x >> 4;
    const int bm = blockIdx.y * 64, bn = blockIdx.x * 64;
    float acc[4][4] = {};
    for (int k0 = 0; k0 < K; k0 += 32) {
#pragma unroll
        for (int i = 0; i < 2; i++) {
            int idx = threadIdx.x + i * 256;
            int r = idx >> 3, kc = (idx & 7) * 4;
            float4 v = *(const float4*)&A[(bm + r) * K + k0 + kc];
            As[kc + 0][r] = v.x; As[kc + 1][r] = v.y;
            As[kc + 2][r] = v.z; As[kc + 3][r] = v.w;
        }
#pragma unroll
        for (int i = 0; i < 2; i++) {
            int idx = threadIdx.x + i * 256;
            int r = idx >> 4, c = (idx & 15) * 4;
            *(float4*)&Bs[r][c] = *(const float4*)&W[(k0 + r) * NC + bn + c];
        }
        __syncthreads();
#pragma unroll
        for (int kk = 0; kk < 32; kk++) {
            float a[4], b[4];
            *(float4*)a = *(const float4*)&As[kk][ty * 4];
            *(float4*)b = *(const float4*)&Bs[kk][tx * 4];
#pragma unroll
            for (int i = 0; i < 4; i++)
#pragma unroll
                for (int j = 0; j < 4; j++) acc[i][j] += a[i] * b[j];
        }
        __syncthreads();
    }
#pragma unroll
    for (int i = 0; i < 4; i++) {
        int row = bm + ty * 4 + i, col = bn + tx * 4;
        if (HOUT) {
            __half* Ch = (__half*)Cv;
            __half2 p0 = __floats2half2_rn(acc[i][0], acc[i][1]);
            __half2 p1 = __floats2half2_rn(acc[i][2], acc[i][3]);
            *(__half2*)&Ch[row * NC + col] = p0;
            *(__half2*)&Ch[row * NC + col + 2] = p1;
        } else {
            float* C = (float*)Cv;
            float4 o;
            float* po = (float*)&o;
#pragma unroll
            for (int j = 0; j < 4; j++) {
                float v = acc[i][j];
                if (EPI) v = fmaxf(v + bias[col + j], 0.f);
                po[j] = v;
            }
            *(float4*)&C[row * NC + col] = o;
        }
    }
}

// ---------------- CSR aggregation from fp16 rows (F=64) ---------------------
// one warp per node; lane covers cols {2*lane, 2*lane+1}; fp32 accumulate.
// Edge loop unrolled x4 for memory-level parallelism (latency-bound loop).
template <bool BR, bool HOUT>
__global__ void k_agg_h64(const __half* __restrict__ t,
                          const float* __restrict__ bias,
                          void* __restrict__ outv) {
    int warp = (blockIdx.x * blockDim.x + threadIdx.x) >> 5;
    int lane = threadIdx.x & 31;
    if (warp >= NNODE) return;
    int e = g_rowptr[warp], end = g_rowptr[warp + 1];
    int c0 = lane * 2;
    float ax = 0.f, ay = 0.f;
    for (; e + 4 <= end; e += 4) {
        int s0 = __ldg(&g_col[e]);
        int s1 = __ldg(&g_col[e + 1]);
        int s2 = __ldg(&g_col[e + 2]);
        int s3 = __ldg(&g_col[e + 3]);
        float w0 = __ldg(&g_dinv[s0]);
        float w1 = __ldg(&g_dinv[s1]);
        float w2 = __ldg(&g_dinv[s2]);
        float w3 = __ldg(&g_dinv[s3]);
        __half2 h0 = __ldg((const __half2*)&t[s0 * NHID + c0]);
        __half2 h1 = __ldg((const __half2*)&t[s1 * NHID + c0]);
        __half2 h2 = __ldg((const __half2*)&t[s2 * NHID + c0]);
        __half2 h3 = __ldg((const __half2*)&t[s3 * NHID + c0]);
        float2 f0 = __half22float2(h0);
        float2 f1 = __half22float2(h1);
        float2 f2 = __half22float2(h2);
        float2 f3 = __half22float2(h3);
        ax += w0 * f0.x + w1 * f1.x + w2 * f2.x + w3 * f3.x;
        ay += w0 * f0.y + w1 * f1.y + w2 * f2.y + w3 * f3.y;
    }
    for (; e < end; e++) {
        int s = __ldg(&g_col[e]);
        float w = __ldg(&g_dinv[s]);
        float2 f = __half22float2(__ldg((const __half2*)&t[s * NHID + c0]));
        ax += w * f.x;
        ay += w * f.y;
    }
    float di = __ldg(&g_dinv[warp]);
    float2 v = make_float2(ax * di, ay * di);
    if (BR) {
        v.x = fmaxf(v.x + __ldg(&bias[c0]), 0.f);
        v.y = fmaxf(v.y + __ldg(&bias[c0 + 1]), 0.f);
    }
    if (HOUT) {
        ((__half2*)outv)[warp * 32 + lane] = __floats2half2_rn(v.x, v.y);
    } else {
        *(float2*)&((float*)outv)[warp * NHID + c0] = v;
    }
}

// ---------------- z @ z.T via fp16 mma (symmetric, lower-tri compute) -------
// 128x128 tile per block, 8 warps (4x2), warp tile 32x64, K=64 in 4 k16 steps.
__global__ void k_zzt_hmma(const __half* __restrict__ Zh, float* __restrict__ C) {
    const int ti = blockIdx.y, tj = blockIdx.x;
    if (tj > ti) return;
    extern __shared__ float sm[];
    __half* Za = (__half*)sm;                 // [128][ZH_LD]
    __half* Zb = (__half*)sm + 128 * ZH_LD;   // [128][ZH_LD]
    const int tid = threadIdx.x;
    const int lane = tid & 31, warp = tid >> 5;
    const int wm = warp >> 1, wn = warp & 1;
    const int m0 = wm * 32, n0 = wn * 64;

#pragma unroll
    for (int i = 0; i < 4; i++) {
        int idx = tid + i * 256;
        int r = idx >> 3, c8 = (idx & 7) * 8;   // 8 halfs = 16 B
        uint4 va = *(const uint4*)&Zh[(size_t)(ti * 128 + r) * 64 + c8];
        uint4 vb = *(const uint4*)&Zh[(size_t)(tj * 128 + r) * 64 + c8];
        *(uint4*)&Za[r * ZH_LD + c8] = va;
        *(uint4*)&Zb[r * ZH_LD + c8] = vb;
    }
    __syncthreads();

    uint32_t a_base = (uint32_t)__cvta_generic_to_shared(Za);
    uint32_t b_base = (uint32_t)__cvta_generic_to_shared(Zb);
    float acc[2][8][4] = {};
#pragma unroll
    for (int ks = 0; ks < 4; ks++) {
        const int k0 = ks * 16;
        uint32_t a[2][4];
#pragma unroll
        for (int f = 0; f < 2; f++) {
            int r = m0 + f * 16 + (lane & 7) + ((lane & 8) ? 8 : 0);
            int kk = k0 + ((lane & 16) ? 8 : 0);
            ldsm_x4(a[f], a_base + (uint32_t)(r * ZH_LD + kk) * 2u);
        }
        uint32_t b[4][4];
#pragma unroll
        for (int p = 0; p < 4; p++) {
            int r = n0 + p * 16 + (lane & 7) + ((lane & 16) ? 8 : 0);
            int kk = k0 + ((lane & 8) ? 8 : 0);
            ldsm_x4(b[p], b_base + (uint32_t)(r * ZH_LD + kk) * 2u);
        }
#pragma unroll
        for (int f = 0; f < 2; f++)
#pragma unroll
            for (int j = 0; j < 8; j++)
                mma_f16(acc[f][j], a[f], b[j >> 1][(j & 1) * 2], b[j >> 1][(j & 1) * 2 + 1]);
    }

    // direct write of tile (ti, tj)
    const int mrow = lane >> 2, ncol2 = (lane & 3) * 2;
#pragma unroll
    for (int f = 0; f < 2; f++) {
        int row0 = ti * 128 + m0 + f * 16 + mrow;
#pragma unroll
        for (int j = 0; j < 8; j++) {
            int col = tj * 128 + n0 + j * 8 + ncol2;
            *(float2*)&C[(size_t)row0 * NNODE + col] =
                make_float2(acc[f][j][0], acc[f][j][1]);
            *(float2*)&C[(size_t)(row0 + 8) * NNODE + col] =
                make_float2(acc[f][j][2], acc[f][j][3]);
        }
    }
    if (ti == tj) return;

    // mirror tile (tj, ti): stride-129 staging -> conflict-free transposed reads
    __syncthreads();
    float* S = sm;  // 128 * 129 floats = 66048 B
#pragma unroll
    for (int f = 0; f < 2; f++) {
        int r = m0 + f * 16 + mrow;
#pragma unroll
        for (int j = 0; j < 8; j++) {
            int c = n0 + j * 8 + ncol2;
            S[r * LDST + c] = acc[f][j][0];
            S[r * LDST + c + 1] = acc[f][j][1];
            S[(r + 8) * LDST + c] = acc[f][j][2];
            S[(r + 8) * LDST + c + 1] = acc[f][j][3];
        }
    }
    __syncthreads();
#pragma unroll
    for (int i = 0; i < 16; i++) {
        int y = warp * 16 + i;
        size_t rowbase = (size_t)(tj * 128 + y) * NNODE + ti * 128;
#pragma unroll
        for (int k = 0; k < 4; k++) {
            int col = lane + 32 * k;
            __stcs(&C[rowbase + col], S[col * LDST + y]);
        }
    }
}

// ---------------- launch ----------------------------------------------------
extern "C" void kernel_launch(void* const* d_in, const int* in_sizes, int n_in,
                              void* d_out, int out_size) {
    const float* x  = (const float*)d_in[0];
    const int*   ei = (const int*)d_in[1];
    const float* W1 = (const float*)d_in[2];
    const float* b1 = (const float*)d_in[3];
    const float* W2 = (const float*)d_in[4];
    const float* b2 = (const float*)d_in[5];
    const float* Wd = (const float*)d_in[6];
    const float* bd = (const float*)d_in[7];
    float* out = (float*)d_out;
    float* xhat = out + (size_t)NNODE * NNODE;

    float*  t;  cudaGetSymbolAddress((void**)&t,  g_t);
    __half* th; cudaGetSymbolAddress((void**)&th, g_th);
    float*  h;  cudaGetSymbolAddress((void**)&h,  g_h);
    __half* zh; cudaGetSymbolAddress((void**)&zh, g_zh);

    const int zzt_smem = 128 * LDST * (int)sizeof(float);  // 66048
    cudaFuncSetAttribute(k_zzt_hmma, cudaFuncAttributeMaxDynamicSharedMemorySize,
                         zzt_smem);

    // one-time side resources (no device memory)
    struct Res {
        cudaStream_t sB;
        cudaEvent_t evA, evB, evC, evD;
        Res() {
            cudaStreamCreateWithFlags(&sB, cudaStreamNonBlocking);
            cudaEventCreateWithFlags(&evA, cudaEventDisableTiming);
            cudaEventCreateWithFlags(&evB, cudaEventDisableTiming);
            cudaEventCreateWithFlags(&evC, cudaEventDisableTiming);
            cudaEventCreateWithFlags(&evD, cudaEventDisableTiming);
        }
    };
    static Res R;

    // ---- fork: CSR build on sB, concurrent with x@W1 on main stream ----
    cudaEventRecord(R.evA, 0);
    cudaStreamWaitEvent(R.sB, R.evA, 0);
    k_init_cnt<<<NNODE / 256, 256, 0, R.sB>>>();
    k_hist<<<NEDGE / 256, 256, 0, R.sB>>>(ei);
    k_scan<<<1, 1024, 0, R.sB>>>();
    k_scatter<<<(NLOOP + 255) / 256, 256, 0, R.sB>>>(ei);
    cudaEventRecord(R.evB, R.sB);

    // layer-1 feature transform, fp16 output
    k_gemm_nn<NIN, NHID, false, true><<<dim3(1, NNODE / 64), 256>>>(x, W1, th, nullptr);

    // ---- join: encoder chain needs CSR + th ----
    cudaStreamWaitEvent(0, R.evB, 0);
    k_agg_h64<true, false><<<NNODE * 32 / 256, 256>>>(th, b1, h);
    k_gemm_nn<NHID, NHID, false, true><<<dim3(1, NNODE / 64), 256>>>(h, W2, th, nullptr);
    // layer-2 aggregation writes z directly as fp16 (zh)
    k_agg_h64<true, true><<<NNODE * 32 / 256, 256>>>(th, b2, zh);

    // ---- fork: attribute decoder on sB, concurrent with z@z.T ----
    // (both read the same L2-resident 2 MB zh; decoder adds only ~25 MB of
    //  traffic vs zzt's 1 GB stream — retrying now that the R9 epilogue fixed
    //  what R5's bundled experiment conflated)
    cudaEventRecord(R.evC, 0);
    cudaStreamWaitEvent(R.sB, R.evC, 0);
    k_agg_h64<false, false><<<NNODE * 32 / 256, 256, 0, R.sB>>>(zh, nullptr, t);
    k_gemm_nn<NHID, NIN, true, false><<<dim3(NIN / 64, NNODE / 64), 256, 0, R.sB>>>(t, Wd, xhat, bd);
    cudaEventRecord(R.evD, R.sB);

    // structure decoder: out = z @ z.T (symmetric, fp16 tensor path, f32 accum)
    k_zzt_hmma<<<dim3(NNODE / 128, NNODE / 128), 256, zzt_smem>>>(zh, out);

    // ---- join before returning to harness ----
    cudaStreamWaitEvent(0, R.evD, 0);
}

// round 13
// speedup vs baseline: 1.0732x; 1.0470x over previous
#include <cuda_runtime.h>
#include <cuda_fp16.h>
#include <math.h>
#include <stdint.h>

#define NNODE 16384
#define NEDGE 1048576
#define NLOOP (NEDGE + NNODE)
#define NIN 256
#define NHID 64
#define ZH_LD 72    // halfs per smem row (144 B stride -> ldmatrix conflict-free)
#define LDST 129    // staging stride (mod 32 == 1 -> transposed reads conflict-free)

// ---------------- scratch (static device memory; no runtime alloc) ----------
__device__ int    g_cnt[NNODE];
__device__ int    g_rowptr[NNODE + 1];
__device__ int    g_off[NNODE];
__device__ int2   g_cw[NLOOP];           // packed {src col, dinv[src] bits}
__device__ float  g_dinv[NNODE];
__device__ float  g_t[NNODE * NIN];      // fp32 scratch (decoder pre-GEMM feats)
__device__ __half g_th[NNODE * NHID];    // fp16 pre-aggregation features
__device__ float  g_h[NNODE * NHID];
__device__ __half g_zh[NNODE * NHID];    // fp16 latent z

// ---------------- ptx helpers ----------------
__device__ __forceinline__ void ldsm_x4(uint32_t r[4], uint32_t addr) {
    asm volatile("ldmatrix.sync.aligned.m8n8.x4.shared.b16 {%0,%1,%2,%3}, [%4];"
                 : "=r"(r[0]), "=r"(r[1]), "=r"(r[2]), "=r"(r[3]) : "r"(addr));
}
__device__ __forceinline__ void mma_f16(float c[4], const uint32_t a[4],
                                        uint32_t b0, uint32_t b1) {
    asm volatile(
        "mma.sync.aligned.m16n8k16.row.col.f32.f16.f16.f32 "
        "{%0,%1,%2,%3},{%4,%5,%6,%7},{%8,%9},{%0,%1,%2,%3};"
        : "+f"(c[0]), "+f"(c[1]), "+f"(c[2]), "+f"(c[3])
        : "r"(a[0]), "r"(a[1]), "r"(a[2]), "r"(a[3]), "r"(b0), "r"(b1));
}

// ---------------- CSR build ----------------
__global__ void k_init_cnt() {
    int i = blockIdx.x * blockDim.x + threadIdx.x;
    if (i < NNODE) g_cnt[i] = 1;  // self-loop
}

__global__ void k_hist(const int* __restrict__ ei) {
    int e = blockIdx.x * blockDim.x + threadIdx.x;
    if (e < NEDGE) atomicAdd(&g_cnt[ei[NEDGE + e]], 1);  // dst row
}

__global__ void k_scan() {
    __shared__ int s[1024];
    int tid = threadIdx.x;
    int base = tid * 16;
    int v[16];
    int tot = 0;
#pragma unroll
    for (int j = 0; j < 16; j++) { v[j] = g_cnt[base + j]; tot += v[j]; }
    s[tid] = tot;
    __syncthreads();
    for (int o = 1; o < 1024; o <<= 1) {
        int add = (tid >= o) ? s[tid - o] : 0;
        __syncthreads();
        s[tid] += add;
        __syncthreads();
    }
    int run = (tid == 0) ? 0 : s[tid - 1];
#pragma unroll
    for (int j = 0; j < 16; j++) {
        g_rowptr[base + j] = run;
        g_off[base + j] = run;
        g_dinv[base + j] = rsqrtf((float)v[j]);
        run += v[j];
    }
    if (tid == 1023) g_rowptr[NNODE] = s[1023];
}

// scatter packed {col, dinv[col]} (dinv is ready: k_scan runs before this)
__global__ void k_scatter(const int* __restrict__ ei) {
    int idx = blockIdx.x * blockDim.x + threadIdx.x;
    if (idx >= NLOOP) return;
    int s, d;
    if (idx < NEDGE) { s = ei[idx]; d = ei[NEDGE + idx]; }
    else             { s = idx - NEDGE; d = s; }
    int p = atomicAdd(&g_off[d], 1);
    g_cw[p] = make_int2(s, __float_as_int(__ldg(&g_dinv[s])));
}

// ---------------- dense GEMM: C[M,NC] = A[M,K] @ W[K,NC] --------------------
// EPI: +bias & relu (fp32 out). HOUT: write fp16 (no bias).
template <int K, int NC, bool EPI, bool HOUT>
__global__ void k_gemm_nn(const float* __restrict__ A, const float* __restrict__ W,
                          void* __restrict__ Cv, const float* __restrict__ bias) {
    __shared__ float As[32][68];
    __shared__ float Bs[32][64];
    const int tx = threadIdx.x & 15, ty = threadIdx.x >> 4;
    const int bm = blockIdx.y * 64, bn = blockIdx.x * 64;
    float acc[4][4] = {};
    for (int k0 = 0; k0 < K; k0 += 32) {
#pragma unroll
        for (int i = 0; i < 2; i++) {
            int idx = threadIdx.x + i * 256;
            int r = idx >> 3, kc = (idx & 7) * 4;
            float4 v = *(const float4*)&A[(bm + r) * K + k0 + kc];
            As[kc + 0][r] = v.x; As[kc + 1][r] = v.y;
            As[kc + 2][r] = v.z; As[kc + 3][r] = v.w;
        }
#pragma unroll
        for (int i = 0; i < 2; i++) {
            int idx = threadIdx.x + i * 256;
            int r = idx >> 4, c = (idx & 15) * 4;
            *(float4*)&Bs[r][c] = *(const float4*)&W[(k0 + r) * NC + bn + c];
        }
        __syncthreads();
#pragma unroll
        for (int kk = 0; kk < 32; kk++) {
            float a[4], b[4];
            *(float4*)a = *(const float4*)&As[kk][ty * 4];
            *(float4*)b = *(const float4*)&Bs[kk][tx * 4];
#pragma unroll
            for (int i = 0; i < 4; i++)
#pragma unroll
                for (int j = 0; j < 4; j++) acc[i][j] += a[i] * b[j];
        }
        __syncthreads();
    }
#pragma unroll
    for (int i = 0; i < 4; i++) {
        int row = bm + ty * 4 + i, col = bn + tx * 4;
        if (HOUT) {
            __half* Ch = (__half*)Cv;
            __half2 p0 = __floats2half2_rn(acc[i][0], acc[i][1]);
            __half2 p1 = __floats2half2_rn(acc[i][2], acc[i][3]);
            *(__half2*)&Ch[row * NC + col] = p0;
            *(__half2*)&Ch[row * NC + col + 2] = p1;
        } else {
            float* C = (float*)Cv;
            float4 o;
            float* po = (float*)&o;
#pragma unroll
            for (int j = 0; j < 4; j++) {
                float v = acc[i][j];
                if (EPI) v = fmaxf(v + bias[col + j], 0.f);
                po[j] = v;
            }
            *(float4*)&C[row * NC + col] = o;
        }
    }
}

// ---------------- CSR aggregation from fp16 rows (F=64) ---------------------
// one warp per node; lane covers cols {2*lane, 2*lane+1}; fp32 accumulate.
// Lane-cooperative edge fetch: per 32-edge chunk one coalesced int2 LDG,
// then shfl-broadcast -> ~1 LDG per edge (row load) instead of 3.
template <bool BR, bool HOUT>
__global__ void k_agg_cw(const __half* __restrict__ t,
                         const float* __restrict__ bias,
                         void* __restrict__ outv) {
    int warp = (blockIdx.x * blockDim.x + threadIdx.x) >> 5;
    int lane = threadIdx.x & 31;
    if (warp >= NNODE) return;
    int e = g_rowptr[warp], end = g_rowptr[warp + 1];
    int c0 = lane * 2;
    float ax = 0.f, ay = 0.f;
    while (e + 32 <= end) {
        int2 cw = __ldg(&g_cw[e + lane]);
#pragma unroll
        for (int k = 0; k < 32; k++) {
            int s = __shfl_sync(0xffffffffu, cw.x, k);
            float w = __int_as_float(__shfl_sync(0xffffffffu, cw.y, k));
            float2 f = __half22float2(__ldg((const __half2*)&t[s * NHID + c0]));
            ax += w * f.x;
            ay += w * f.y;
        }
        e += 32;
    }
    if (e < end) {
        int n = end - e;
        int2 cw = (lane < n) ? __ldg(&g_cw[e + lane]) : make_int2(0, 0);
        for (int k = 0; k < n; k++) {
            int s = __shfl_sync(0xffffffffu, cw.x, k);
            float w = __int_as_float(__shfl_sync(0xffffffffu, cw.y, k));
            float2 f = __half22float2(__ldg((const __half2*)&t[s * NHID + c0]));
            ax += w * f.x;
            ay += w * f.y;
        }
    }
    float di = __ldg(&g_dinv[warp]);
    float2 v = make_float2(ax * di, ay * di);
    if (BR) {
        v.x = fmaxf(v.x + __ldg(&bias[c0]), 0.f);
        v.y = fmaxf(v.y + __ldg(&bias[c0 + 1]), 0.f);
    }
    if (HOUT) {
        ((__half2*)outv)[warp * 32 + lane] = __floats2half2_rn(v.x, v.y);
    } else {
        *(float2*)&((float*)outv)[warp * NHID + c0] = v;
    }
}

// ---------------- z @ z.T via fp16 mma (symmetric, lower-tri compute) -------
// 128x128 tile per block, 8 warps (4x2), warp tile 32x64, K=64 in 4 k16 steps.
__global__ void k_zzt_hmma(const __half* __restrict__ Zh, float* __restrict__ C) {
    const int ti = blockIdx.y, tj = blockIdx.x;
    if (tj > ti) return;
    extern __shared__ float sm[];
    __half* Za = (__half*)sm;                 // [128][ZH_LD]
    __half* Zb = (__half*)sm + 128 * ZH_LD;   // [128][ZH_LD]
    const int tid = threadIdx.x;
    const int lane = tid & 31, warp = tid >> 5;
    const int wm = warp >> 1, wn = warp & 1;
    const int m0 = wm * 32, n0 = wn * 64;

#pragma unroll
    for (int i = 0; i < 4; i++) {
        int idx = tid + i * 256;
        int r = idx >> 3, c8 = (idx & 7) * 8;   // 8 halfs = 16 B
        uint4 va = *(const uint4*)&Zh[(size_t)(ti * 128 + r) * 64 + c8];
        uint4 vb = *(const uint4*)&Zh[(size_t)(tj * 128 + r) * 64 + c8];
        *(uint4*)&Za[r * ZH_LD + c8] = va;
        *(uint4*)&Zb[r * ZH_LD + c8] = vb;
    }
    __syncthreads();

    uint32_t a_base = (uint32_t)__cvta_generic_to_shared(Za);
    uint32_t b_base = (uint32_t)__cvta_generic_to_shared(Zb);
    float acc[2][8][4] = {};
#pragma unroll
    for (int ks = 0; ks < 4; ks++) {
        const int k0 = ks * 16;
        uint32_t a[2][4];
#pragma unroll
        for (int f = 0; f < 2; f++) {
            int r = m0 + f * 16 + (lane & 7) + ((lane & 8) ? 8 : 0);
            int kk = k0 + ((lane & 16) ? 8 : 0);
            ldsm_x4(a[f], a_base + (uint32_t)(r * ZH_LD + kk) * 2u);
        }
        uint32_t b[4][4];
#pragma unroll
        for (int p = 0; p < 4; p++) {
            int r = n0 + p * 16 + (lane & 7) + ((lane & 16) ? 8 : 0);
            int kk = k0 + ((lane & 8) ? 8 : 0);
            ldsm_x4(b[p], b_base + (uint32_t)(r * ZH_LD + kk) * 2u);
        }
#pragma unroll
        for (int f = 0; f < 2; f++)
#pragma unroll
            for (int j = 0; j < 8; j++)
                mma_f16(acc[f][j], a[f], b[j >> 1][(j & 1) * 2], b[j >> 1][(j & 1) * 2 + 1]);
    }

    // direct write of tile (ti, tj): streaming stores (evict-first)
    const int mrow = lane >> 2, ncol2 = (lane & 3) * 2;
#pragma unroll
    for (int f = 0; f < 2; f++) {
        int row0 = ti * 128 + m0 + f * 16 + mrow;
#pragma unroll
        for (int j = 0; j < 8; j++) {
            int col = tj * 128 + n0 + j * 8 + ncol2;
            __stcs((float2*)&C[(size_t)row0 * NNODE + col],
                   make_float2(acc[f][j][0], acc[f][j][1]));
            __stcs((float2*)&C[(size_t)(row0 + 8) * NNODE + col],
                   make_float2(acc[f][j][2], acc[f][j][3]));
        }
    }
    if (ti == tj) return;

    // mirror tile (tj, ti): stride-129 staging -> conflict-free transposed reads
    __syncthreads();
    float* S = sm;  // 128 * 129 floats = 66048 B
#pragma unroll
    for (int f = 0; f < 2; f++) {
        int r = m0 + f * 16 + mrow;
#pragma unroll
        for (int j = 0; j < 8; j++) {
            int c = n0 + j * 8 + ncol2;
            S[r * LDST + c] = acc[f][j][0];
            S[r * LDST + c + 1] = acc[f][j][1];
            S[(r + 8) * LDST + c] = acc[f][j][2];
            S[(r + 8) * LDST + c + 1] = acc[f][j][3];
        }
    }
    __syncthreads();
#pragma unroll
    for (int i = 0; i < 16; i++) {
        int y = warp * 16 + i;
        size_t rowbase = (size_t)(tj * 128 + y) * NNODE + ti * 128;
#pragma unroll
        for (int k = 0; k < 4; k++) {
            int col = lane + 32 * k;
            __stcs(&C[rowbase + col], S[col * LDST + y]);
        }
    }
}

// ---------------- launch ----------------------------------------------------
extern "C" void kernel_launch(void* const* d_in, const int* in_sizes, int n_in,
                              void* d_out, int out_size) {
    const float* x  = (const float*)d_in[0];
    const int*   ei = (const int*)d_in[1];
    const float* W1 = (const float*)d_in[2];
    const float* b1 = (const float*)d_in[3];
    const float* W2 = (const float*)d_in[4];
    const float* b2 = (const float*)d_in[5];
    const float* Wd = (const float*)d_in[6];
    const float* bd = (const float*)d_in[7];
    float* out = (float*)d_out;
    float* xhat = out + (size_t)NNODE * NNODE;

    float*  t;  cudaGetSymbolAddress((void**)&t,  g_t);
    __half* th; cudaGetSymbolAddress((void**)&th, g_th);
    float*  h;  cudaGetSymbolAddress((void**)&h,  g_h);
    __half* zh; cudaGetSymbolAddress((void**)&zh, g_zh);

    const int zzt_smem = 128 * LDST * (int)sizeof(float);  // 66048
    cudaFuncSetAttribute(k_zzt_hmma, cudaFuncAttributeMaxDynamicSharedMemorySize,
                         zzt_smem);

    // one-time side resources (no device memory)
    struct Res {
        cudaStream_t sB;
        cudaEvent_t evA, evB, evC, evD;
        Res() {
            cudaStreamCreateWithFlags(&sB, cudaStreamNonBlocking);
            cudaEventCreateWithFlags(&evA, cudaEventDisableTiming);
            cudaEventCreateWithFlags(&evB, cudaEventDisableTiming);
            cudaEventCreateWithFlags(&evC, cudaEventDisableTiming);
            cudaEventCreateWithFlags(&evD, cudaEventDisableTiming);
        }
    };
    static Res R;

    // ---- fork: CSR build on sB, concurrent with x@W1 on main stream ----
    cudaEventRecord(R.evA, 0);
    cudaStreamWaitEvent(R.sB, R.evA, 0);
    k_init_cnt<<<NNODE / 256, 256, 0, R.sB>>>();
    k_hist<<<NEDGE / 256, 256, 0, R.sB>>>(ei);
    k_scan<<<1, 1024, 0, R.sB>>>();
    k_scatter<<<(NLOOP + 255) / 256, 256, 0, R.sB>>>(ei);
    cudaEventRecord(R.evB, R.sB);

    // layer-1 feature transform, fp16 output
    k_gemm_nn<NIN, NHID, false, true><<<dim3(1, NNODE / 64), 256>>>(x, W1, th, nullptr);

    // ---- join: encoder chain needs CSR + th ----
    cudaStreamWaitEvent(0, R.evB, 0);
    k_agg_cw<true, false><<<NNODE * 32 / 256, 256>>>(th, b1, h);
    k_gemm_nn<NHID, NHID, false, true><<<dim3(1, NNODE / 64), 256>>>(h, W2, th, nullptr);
    // layer-2 aggregation writes z directly as fp16 (zh)
    k_agg_cw<true, true><<<NNODE * 32 / 256, 256>>>(th, b2, zh);

    // ---- fork: attribute decoder on sB, concurrent with z@z.T ----
    cudaEventRecord(R.evC, 0);
    cudaStreamWaitEvent(R.sB, R.evC, 0);
    k_agg_cw<false, false><<<NNODE * 32 / 256, 256, 0, R.sB>>>(zh, nullptr, t);
    k_gemm_nn<NHID, NIN, true, false><<<dim3(NIN / 64, NNODE / 64), 256, 0, R.sB>>>(t, Wd, xhat, bd);
    cudaEventRecord(R.evD, R.sB);

    // structure decoder: out = z @ z.T (symmetric, fp16 tensor path, f32 accum)
    k_zzt_hmma<<<dim3(NNODE / 128, NNODE / 128), 256, zzt_smem>>>(zh, out);

    // ---- join before returning to harness ----
    cudaStreamWaitEvent(0, R.evD, 0);
}